// round 7
// baseline (speedup 1.0000x reference)
#include <cuda_runtime.h>
#include <cuda_fp16.h>
#include <cstdint>

// ---------------- problem constants ------------------------------------------
#define B_ 4
#define S_ 2048
#define D_ 512
#define H_ 8
#define NT 8192               // B*S tokens
#define DH 4096               // D*H
#define ZN 32                 // B*H attention instances
#define ATT_SCALE 0.04419417382415922f   // 512^-0.5

// ---------------- scratch (device globals; no runtime allocation) -------------
__device__ __half g_xn[(size_t)NT * D_];               // 8 MB
__device__ __half g_q[(size_t)ZN * S_ * D_];           // 64 MB [z][s][d] (pre-scaled)
__device__ __half g_k[(size_t)ZN * S_ * D_];           // 64 MB [z][s][d]
__device__ __half g_v[(size_t)ZN * S_ * D_];           // 64 MB [z][s][d]
__device__ __half g_vt[(size_t)ZN * S_ * D_];          // 64 MB [z][d][s]
__device__ __half g_p[(size_t)ZN * S_ * S_];           // 256 MB fp16 exp(logits)
__device__ float  g_partial[(size_t)ZN * S_ * 32];     // 8 MB per-row partial sums
__device__ float  g_rowsum[(size_t)ZN * S_];           // 256 KB 1/rowsum
__device__ __half g_attn[(size_t)NT * DH];             // 64 MB [token][h*512+d]
__device__ __half g_wtq[(size_t)DH * D_];              // 4 MB  W^T [4096][512]
__device__ __half g_wtk[(size_t)DH * D_];
__device__ __half g_wtv[(size_t)DH * D_];
__device__ __half g_wto[(size_t)D_ * DH];              // 4 MB  o_w^T [512][4096]

// ---------------- helpers -----------------------------------------------------
__device__ __forceinline__ uint32_t smem_u32(const void* p) {
    uint32_t a;
    asm("{ .reg .u64 t; cvta.to.shared.u64 t, %1; cvt.u32.u64 %0, t; }" : "=r"(a) : "l"(p));
    return a;
}
__device__ __forceinline__ void cp16(uint32_t dst, const void* src) {
    asm volatile("cp.async.cg.shared.global [%0], [%1], 16;" :: "r"(dst), "l"(src));
}
#define CP_COMMIT() asm volatile("cp.async.commit_group;")
#define CP_WAIT1()  asm volatile("cp.async.wait_group 1;")

__device__ __forceinline__ void ldsm_x4(uint32_t* r, uint32_t addr) {
    asm volatile("ldmatrix.sync.aligned.m8n8.x4.shared.b16 {%0,%1,%2,%3}, [%4];"
        : "=r"(r[0]), "=r"(r[1]), "=r"(r[2]), "=r"(r[3]) : "r"(addr));
}
__device__ __forceinline__ void mma_f16(float* c, const uint32_t* a, const uint32_t* b) {
    asm volatile(
        "mma.sync.aligned.m16n8k16.row.col.f32.f16.f16.f32 "
        "{%0,%1,%2,%3}, {%4,%5,%6,%7}, {%8,%9}, {%0,%1,%2,%3};"
        : "+f"(c[0]), "+f"(c[1]), "+f"(c[2]), "+f"(c[3])
        : "r"(a[0]), "r"(a[1]), "r"(a[2]), "r"(a[3]), "r"(b[0]), "r"(b[1]));
}

// ---------------- LayerNorm (fp32 in -> fp16 out) -----------------------------
__global__ void ln_kernel(const float* __restrict__ x,
                          const float* __restrict__ w,
                          const float* __restrict__ b) {
    int row = blockIdx.x;
    int t = threadIdx.x;                       // 128 threads, 4 floats each
    const float4* xr = (const float4*)(x + (size_t)row * D_);
    float4 v = xr[t];
    float s  = v.x + v.y + v.z + v.w;
    float q  = v.x * v.x + v.y * v.y + v.z * v.z + v.w * v.w;
#pragma unroll
    for (int o = 16; o > 0; o >>= 1) {
        s += __shfl_xor_sync(0xffffffffu, s, o);
        q += __shfl_xor_sync(0xffffffffu, q, o);
    }
    __shared__ float ss[4], sq[4];
    int wid = t >> 5;
    if ((t & 31) == 0) { ss[wid] = s; sq[wid] = q; }
    __syncthreads();
    s = ss[0] + ss[1] + ss[2] + ss[3];
    q = sq[0] + sq[1] + sq[2] + sq[3];
    float mu  = s * (1.0f / D_);
    float var = q * (1.0f / D_) - mu * mu;
    float r   = rsqrtf(var + 1e-5f);
    float4 wv = ((const float4*)w)[t];
    float4 bv = ((const float4*)b)[t];
    __half2 h0 = __floats2half2_rn((v.x - mu) * r * wv.x + bv.x,
                                   (v.y - mu) * r * wv.y + bv.y);
    __half2 h1 = __floats2half2_rn((v.z - mu) * r * wv.z + bv.z,
                                   (v.w - mu) * r * wv.w + bv.w);
    __half2* dst = (__half2*)(g_xn + (size_t)row * D_);
    dst[2 * t]     = h0;
    dst[2 * t + 1] = h1;
}

// ---------------- 32x32 tiled transpose ---------------------------------------
// sel 0..3: fp32 weights in -> half out. sel 4: half V -> half Vt per z.
__global__ void transpose_kernel(const float* __restrict__ in_f32, int sel, int R, int C) {
    __shared__ float tile[32][33];
    int z = blockIdx.z;
    __half* out;
    const __half* in_h = nullptr;
    if (sel == 0)      out = g_wtq;
    else if (sel == 1) out = g_wtk;
    else if (sel == 2) out = g_wtv;
    else if (sel == 3) out = g_wto;
    else { in_h = g_v + (size_t)z * S_ * D_; out = g_vt + (size_t)z * S_ * D_; }

    int x  = blockIdx.x * 32 + threadIdx.x;
    int y0 = blockIdx.y * 32;
#pragma unroll
    for (int j = 0; j < 32; j += 8) {
        float v;
        if (sel < 4) v = in_f32[(size_t)(y0 + threadIdx.y + j) * C + x];
        else         v = __half2float(in_h[(size_t)(y0 + threadIdx.y + j) * C + x]);
        tile[threadIdx.y + j][threadIdx.x] = v;
    }
    __syncthreads();
    int ox  = y0 + threadIdx.x;
    int oy0 = blockIdx.x * 32;
#pragma unroll
    for (int j = 0; j < 32; j += 8)
        out[(size_t)(oy0 + threadIdx.y + j) * R + ox] =
            __float2half_rn(tile[threadIdx.x][threadIdx.y + j]);
}

// ---------------- rowsum reduce: g_partial[row][32] -> 1/sum ------------------
__global__ void rowsum_kernel() {
    int row = blockIdx.x * 128 + threadIdx.x;            // 65536 rows
    const float4* p = (const float4*)(g_partial + (size_t)row * 32);
    float s = 0.f;
#pragma unroll
    for (int i = 0; i < 8; i++) {
        float4 v = p[i];
        s += (v.x + v.y) + (v.z + v.w);
    }
    g_rowsum[row] = 1.0f / s;
}

// ---------------- fp16 mma.sync GEMM, 128x256 tile, 3-stage pipeline ----------
// Both operands K-major fp16. A [M,K], B [N,K]. fp32 accumulate.
// 8 warps (2x4), warp tile 64x64.
// MODE 0: g_xn @ Wt(which)^T -> q(/scale)/k/v half (+bias)
// MODE 1: Qs @ K^T -> exp -> g_p fp16 + row partial sums (per z)
// MODE 2: E @ Vt^T * (1/rowsum) -> g_attn half (per z)
// MODE 3: g_attn @ Wto^T     -> out fp32 (+bias)
constexpr int STG = 3;
constexpr int ABYTES = 128 * 40 * 2;             // A tile: 10240 B
constexpr int BBYTES = 256 * 40 * 2;             // B tile: 20480 B
constexpr int STGBYTES = ABYTES + BBYTES;        // 30720 B
constexpr int GEMM_SMEM = STG * STGBYTES;        // 92160 B

template <int MODE>
__global__ __launch_bounds__(256, 1)
void gemm_tc(const float* __restrict__ bias, float* __restrict__ Cout, int which) {
    constexpr int K   = (MODE == 0) ? 512 : (MODE == 1) ? 512 : (MODE == 2) ? 2048 : 4096;
    constexpr int lda = (MODE == 2) ? 2048 : (MODE == 3) ? 4096 : 512;
    constexpr int ldb = (MODE == 2) ? 2048 : (MODE == 3) ? 4096 : 512;
    constexpr int T   = K / 32;

    extern __shared__ __half sh[];
    uint32_t sbase = smem_u32(sh);

    int tid = threadIdx.x;
    int lane = tid & 31, wid = tid >> 5;
    int warp_m = wid & 1, warp_n = wid >> 1;   // 2 x 4 warps -> 64 x 64 per warp
    int z = blockIdx.z;
    int m0 = blockIdx.y * 128, n0 = blockIdx.x * 256;

    const __half* A;
    const __half* Bm;
    if (MODE == 0)      { A = g_xn;
                          Bm = (which == 0) ? g_wtq : (which == 1) ? g_wtk : g_wtv; }
    else if (MODE == 1) { A = g_q + (size_t)z * S_ * D_; Bm = g_k + (size_t)z * S_ * D_; }
    else if (MODE == 2) { A = g_p + ((size_t)z << 22);   Bm = g_vt + (size_t)z * S_ * D_; }
    else                { A = g_attn; Bm = g_wto; }
    A  += (size_t)m0 * lda;
    Bm += (size_t)n0 * ldb;

    float c[4][8][4];
#pragma unroll
    for (int i = 0; i < 4; i++)
#pragma unroll
        for (int j = 0; j < 8; j++)
#pragma unroll
            for (int e = 0; e < 4; e++) c[i][j][e] = 0.0f;

    // tile fill: A 128 rows, B 256 rows; 32 halves (4 x 16B segs) per row
    int lrow = tid >> 2, lseg = tid & 3;       // lrow 0..63
    auto tile_load = [&](int stg, int k0) {
        uint32_t abase = sbase + (uint32_t)stg * STGBYTES;
        uint32_t bbase = abase + ABYTES;
        uint32_t off = (uint32_t)lrow * 80 + (uint32_t)lseg * 16;
#pragma unroll
        for (int i = 0; i < 2; i++)
            cp16(abase + off + (uint32_t)i * 64 * 80,
                 A + (size_t)(lrow + i * 64) * lda + k0 + lseg * 8);
#pragma unroll
        for (int i = 0; i < 4; i++)
            cp16(bbase + off + (uint32_t)i * 64 * 80,
                 Bm + (size_t)(lrow + i * 64) * ldb + k0 + lseg * 8);
        CP_COMMIT();
    };

    // ldmatrix lane geometry (byte offsets within one operand tile)
    int rowA = warp_m * 64 + (lane & 7) + ((lane & 8) ? 8 : 0);
    int kA   = (lane & 16) ? 8 : 0;
    int rowB = warp_n * 64 + (lane & 7) + ((lane & 16) ? 8 : 0);
    int kB   = (lane & 8) ? 8 : 0;

    // prologue: prefetch STG-1 tiles
    tile_load(0, 0);
    tile_load(1, 32);

    for (int t = 0; t < T; t++) {
        int buf = t % STG;
        CP_WAIT1();                 // stage t landed (tail commits are empty groups)
        __syncthreads();            // all warps done with the buffer being refilled
        {
            int tn = t + STG - 1;
            if (tn < T) tile_load(tn % STG, tn * 32);
            else        CP_COMMIT();      // empty group keeps the wait count aligned
        }

        uint32_t abase = sbase + (uint32_t)buf * STGBYTES;
        uint32_t bbase = abase + ABYTES;
#pragma unroll
        for (int kf = 0; kf < 2; kf++) {
            uint32_t a[4][4], b[4][4];
#pragma unroll
            for (int im = 0; im < 4; im++)
                ldsm_x4(a[im], abase + (uint32_t)(rowA + im * 16) * 80
                                     + (uint32_t)(kA + kf * 16) * 2);
#pragma unroll
            for (int jp = 0; jp < 4; jp++)
                ldsm_x4(b[jp], bbase + (uint32_t)(rowB + jp * 16) * 80
                                     + (uint32_t)(kB + kf * 16) * 2);
#pragma unroll
            for (int im = 0; im < 4; im++)
#pragma unroll
                for (int jn = 0; jn < 8; jn++)
                    mma_f16(c[im][jn], a[im], &b[jn >> 1][(jn & 1) * 2]);
        }
    }
    __syncthreads();

    // ---- epilogue: thread owns cols (cc, cc+1) at rows r0 and r0+8 ----
    float rs[4][2];
    if (MODE == 1) {
#pragma unroll
        for (int i = 0; i < 4; i++) { rs[i][0] = 0.f; rs[i][1] = 0.f; }
    }
#pragma unroll
    for (int im = 0; im < 4; im++) {
#pragma unroll
        for (int jn = 0; jn < 8; jn++) {
            int r0 = m0 + warp_m * 64 + im * 16 + (lane >> 2);
            int cc = n0 + warp_n * 64 + jn * 8 + (lane & 3) * 2;
            float2 lo = make_float2(c[im][jn][0], c[im][jn][1]);
            float2 hi = make_float2(c[im][jn][2], c[im][jn][3]);

            if (MODE == 0) {
                float2 bv = *(const float2*)&bias[cc];
                lo.x += bv.x; lo.y += bv.y;
                hi.x += bv.x; hi.y += bv.y;
                if (which == 0) {   // pre-scale Q
                    lo.x *= ATT_SCALE; lo.y *= ATT_SCALE;
                    hi.x *= ATT_SCALE; hi.y *= ATT_SCALE;
                }
                __half* C = (which == 0) ? g_q : (which == 1) ? g_k : g_v;
                int h = cc >> 9, d = cc & 511;
                int b0 = r0 >> 11, s0 = r0 & 2047;
                *(__half2*)(C + ((size_t)(b0 * 8 + h) * S_ + s0) * D_ + d) =
                    __floats2half2_rn(lo.x, lo.y);
                int b1 = (r0 + 8) >> 11, s1 = (r0 + 8) & 2047;
                *(__half2*)(C + ((size_t)(b1 * 8 + h) * S_ + s1) * D_ + d) =
                    __floats2half2_rn(hi.x, hi.y);
            } else if (MODE == 1) {
                // unnormalized softmax numerator: exp(logit), fp16 store
                float e0 = __expf(lo.x), e1 = __expf(lo.y);
                float e2 = __expf(hi.x), e3 = __expf(hi.y);
                rs[im][0] += e0 + e1;
                rs[im][1] += e2 + e3;
                __half* base = g_p + ((size_t)z << 22) + cc;
                *(__half2*)(base + (size_t)r0 * S_) = __floats2half2_rn(e0, e1);
                *(__half2*)(base + (size_t)(r0 + 8) * S_) = __floats2half2_rn(e2, e3);
            } else if (MODE == 2) {
                float inv0 = g_rowsum[(size_t)z * S_ + r0];
                float inv1 = g_rowsum[(size_t)z * S_ + r0 + 8];
                lo.x *= inv0; lo.y *= inv0;
                hi.x *= inv1; hi.y *= inv1;
                int b = z >> 3, h = z & 7;
                __half* base = g_attn + (size_t)(b * S_) * DH + h * 512 + cc;
                *(__half2*)(base + (size_t)r0 * DH) = __floats2half2_rn(lo.x, lo.y);
                *(__half2*)(base + (size_t)(r0 + 8) * DH) = __floats2half2_rn(hi.x, hi.y);
            } else {
                float2 bv = *(const float2*)&bias[cc];
                lo.x += bv.x; lo.y += bv.y;
                hi.x += bv.x; hi.y += bv.y;
                *(float2*)(Cout + (size_t)r0 * D_ + cc) = lo;
                *(float2*)(Cout + (size_t)(r0 + 8) * D_ + cc) = hi;
            }
        }
    }

    if (MODE == 1) {
        // quad-reduce: lanes sharing a row differ only in (lane & 3)
#pragma unroll
        for (int im = 0; im < 4; im++) {
#pragma unroll
            for (int h2 = 0; h2 < 2; h2++) {
                float v = rs[im][h2];
                v += __shfl_xor_sync(0xffffffffu, v, 1);
                v += __shfl_xor_sync(0xffffffffu, v, 2);
                if ((lane & 3) == 0) {
                    int grow = m0 + warp_m * 64 + im * 16 + (lane >> 2) + h2 * 8;
                    g_partial[((size_t)z * S_ + grow) * 32 + blockIdx.x * 4 + warp_n] = v;
                }
            }
        }
    }
}

// ---------------- launch ------------------------------------------------------
extern "C" void kernel_launch(void* const* d_in, const int* in_sizes, int n_in,
                              void* d_out, int out_size) {
    const float* x    = (const float*)d_in[0];
    const float* ln_w = (const float*)d_in[1];
    const float* ln_b = (const float*)d_in[2];
    const float* q_w  = (const float*)d_in[3];
    const float* q_b  = (const float*)d_in[4];
    const float* k_w  = (const float*)d_in[5];
    const float* k_b  = (const float*)d_in[6];
    const float* v_w  = (const float*)d_in[7];
    const float* v_b  = (const float*)d_in[8];
    const float* o_w  = (const float*)d_in[9];
    const float* o_b  = (const float*)d_in[10];
    float* out = (float*)d_out;

    static bool attr_done = false;
    if (!attr_done) {
        cudaFuncSetAttribute(gemm_tc<0>, cudaFuncAttributeMaxDynamicSharedMemorySize, GEMM_SMEM);
        cudaFuncSetAttribute(gemm_tc<1>, cudaFuncAttributeMaxDynamicSharedMemorySize, GEMM_SMEM);
        cudaFuncSetAttribute(gemm_tc<2>, cudaFuncAttributeMaxDynamicSharedMemorySize, GEMM_SMEM);
        cudaFuncSetAttribute(gemm_tc<3>, cudaFuncAttributeMaxDynamicSharedMemorySize, GEMM_SMEM);
        attr_done = true;
    }

    dim3 tb(32, 8);
    ln_kernel<<<NT, 128>>>(x, ln_w, ln_b);
    transpose_kernel<<<dim3(128, 16, 1), tb>>>(q_w, 0, 512, 4096);
    transpose_kernel<<<dim3(128, 16, 1), tb>>>(k_w, 1, 512, 4096);
    transpose_kernel<<<dim3(128, 16, 1), tb>>>(v_w, 2, 512, 4096);
    transpose_kernel<<<dim3(16, 128, 1), tb>>>(o_w, 3, 4096, 512);

    dim3 gQKV(DH / 256, NT / 128, 1);                      // (16, 64)
    gemm_tc<0><<<gQKV, 256, GEMM_SMEM>>>(q_b, nullptr, 0);
    gemm_tc<0><<<gQKV, 256, GEMM_SMEM>>>(k_b, nullptr, 1);
    gemm_tc<0><<<gQKV, 256, GEMM_SMEM>>>(v_b, nullptr, 2);

    // V transpose per z: [2048,512] -> [512,2048]
    transpose_kernel<<<dim3(16, 64, ZN), tb>>>(nullptr, 4, 2048, 512);

    dim3 gS(S_ / 256, S_ / 128, ZN);                       // (8, 16, 32)
    gemm_tc<1><<<gS, 256, GEMM_SMEM>>>(nullptr, nullptr, 0);

    rowsum_kernel<<<ZN * S_ / 128, 128>>>();

    dim3 gPV(D_ / 256, S_ / 128, ZN);                      // (2, 16, 32)
    gemm_tc<2><<<gPV, 256, GEMM_SMEM>>>(nullptr, nullptr, 0);

    dim3 gO(D_ / 256, NT / 128, 1);                        // (2, 64)
    gemm_tc<3><<<gO, 256, GEMM_SMEM>>>(o_b, out, 0);
}

// round 8
// speedup vs baseline: 1.2829x; 1.2829x over previous
#include <cuda_runtime.h>
#include <cuda_fp16.h>
#include <cstdint>

// ---------------- problem constants ------------------------------------------
#define B_ 4
#define S_ 2048
#define D_ 512
#define H_ 8
#define NT 8192               // B*S tokens
#define DH 4096               // D*H
#define ZN 32                 // B*H attention instances
#define ATT_SCALE 0.04419417382415922f   // 512^-0.5

// ---------------- scratch (device globals; no runtime allocation) -------------
__device__ __half g_xn[(size_t)NT * D_];               // 8 MB
__device__ __half g_q[(size_t)ZN * S_ * D_];           // 64 MB [z][s][d] (pre-scaled)
__device__ __half g_k[(size_t)ZN * S_ * D_];           // 64 MB [z][s][d]
__device__ __half g_v[(size_t)ZN * S_ * D_];           // 64 MB [z][s][d]
__device__ __half g_vt[(size_t)ZN * S_ * D_];          // 64 MB [z][d][s]
__device__ __half g_p[(size_t)ZN * S_ * S_];           // 256 MB fp16 exp(logits)
__device__ float  g_partial[(size_t)ZN * S_ * 32];     // 8 MB per-row partial sums
__device__ float  g_rowsum[(size_t)ZN * S_];           // 256 KB 1/rowsum
__device__ __half g_attn[(size_t)NT * DH];             // 64 MB [token][h*512+d]
__device__ __half g_wtq[(size_t)DH * D_];              // 4 MB  W^T [4096][512]
__device__ __half g_wtk[(size_t)DH * D_];
__device__ __half g_wtv[(size_t)DH * D_];
__device__ __half g_wto[(size_t)D_ * DH];              // 4 MB  o_w^T [512][4096]

// ---------------- helpers -----------------------------------------------------
__device__ __forceinline__ uint32_t smem_u32(const void* p) {
    uint32_t a;
    asm("{ .reg .u64 t; cvta.to.shared.u64 t, %1; cvt.u32.u64 %0, t; }" : "=r"(a) : "l"(p));
    return a;
}
__device__ __forceinline__ void cp16(uint32_t dst, const void* src) {
    asm volatile("cp.async.cg.shared.global [%0], [%1], 16;" :: "r"(dst), "l"(src));
}
#define CP_COMMIT() asm volatile("cp.async.commit_group;")
#define CP_WAIT2()  asm volatile("cp.async.wait_group 2;")

__device__ __forceinline__ void ldsm_x4(uint32_t* r, uint32_t addr) {
    asm volatile("ldmatrix.sync.aligned.m8n8.x4.shared.b16 {%0,%1,%2,%3}, [%4];"
        : "=r"(r[0]), "=r"(r[1]), "=r"(r[2]), "=r"(r[3]) : "r"(addr));
}
__device__ __forceinline__ void mma_f16(float* c, const uint32_t* a, const uint32_t* b) {
    asm volatile(
        "mma.sync.aligned.m16n8k16.row.col.f32.f16.f16.f32 "
        "{%0,%1,%2,%3}, {%4,%5,%6,%7}, {%8,%9}, {%0,%1,%2,%3};"
        : "+f"(c[0]), "+f"(c[1]), "+f"(c[2]), "+f"(c[3])
        : "r"(a[0]), "r"(a[1]), "r"(a[2]), "r"(a[3]), "r"(b[0]), "r"(b[1]));
}

// ---------------- LayerNorm (fp32 in -> fp16 out) -----------------------------
__global__ void ln_kernel(const float* __restrict__ x,
                          const float* __restrict__ w,
                          const float* __restrict__ b) {
    int row = blockIdx.x;
    int t = threadIdx.x;                       // 128 threads, 4 floats each
    const float4* xr = (const float4*)(x + (size_t)row * D_);
    float4 v = xr[t];
    float s  = v.x + v.y + v.z + v.w;
    float q  = v.x * v.x + v.y * v.y + v.z * v.z + v.w * v.w;
#pragma unroll
    for (int o = 16; o > 0; o >>= 1) {
        s += __shfl_xor_sync(0xffffffffu, s, o);
        q += __shfl_xor_sync(0xffffffffu, q, o);
    }
    __shared__ float ss[4], sq[4];
    int wid = t >> 5;
    if ((t & 31) == 0) { ss[wid] = s; sq[wid] = q; }
    __syncthreads();
    s = ss[0] + ss[1] + ss[2] + ss[3];
    q = sq[0] + sq[1] + sq[2] + sq[3];
    float mu  = s * (1.0f / D_);
    float var = q * (1.0f / D_) - mu * mu;
    float r   = rsqrtf(var + 1e-5f);
    float4 wv = ((const float4*)w)[t];
    float4 bv = ((const float4*)b)[t];
    __half2 h0 = __floats2half2_rn((v.x - mu) * r * wv.x + bv.x,
                                   (v.y - mu) * r * wv.y + bv.y);
    __half2 h1 = __floats2half2_rn((v.z - mu) * r * wv.z + bv.z,
                                   (v.w - mu) * r * wv.w + bv.w);
    __half2* dst = (__half2*)(g_xn + (size_t)row * D_);
    dst[2 * t]     = h0;
    dst[2 * t + 1] = h1;
}

// ---------------- 32x32 tiled transpose ---------------------------------------
// sel 0..3: fp32 weights in -> half out. sel 4: half V -> half Vt per z.
__global__ void transpose_kernel(const float* __restrict__ in_f32, int sel, int R, int C) {
    __shared__ float tile[32][33];
    int z = blockIdx.z;
    __half* out;
    const __half* in_h = nullptr;
    if (sel == 0)      out = g_wtq;
    else if (sel == 1) out = g_wtk;
    else if (sel == 2) out = g_wtv;
    else if (sel == 3) out = g_wto;
    else { in_h = g_v + (size_t)z * S_ * D_; out = g_vt + (size_t)z * S_ * D_; }

    int x  = blockIdx.x * 32 + threadIdx.x;
    int y0 = blockIdx.y * 32;
#pragma unroll
    for (int j = 0; j < 32; j += 8) {
        float v;
        if (sel < 4) v = in_f32[(size_t)(y0 + threadIdx.y + j) * C + x];
        else         v = __half2float(in_h[(size_t)(y0 + threadIdx.y + j) * C + x]);
        tile[threadIdx.y + j][threadIdx.x] = v;
    }
    __syncthreads();
    int ox  = y0 + threadIdx.x;
    int oy0 = blockIdx.x * 32;
#pragma unroll
    for (int j = 0; j < 32; j += 8)
        out[(size_t)(oy0 + threadIdx.y + j) * R + ox] =
            __float2half_rn(tile[threadIdx.x][threadIdx.y + j]);
}

// ---------------- rowsum reduce: g_partial[row][32] -> 1/sum ------------------
__global__ void rowsum_kernel() {
    int row = blockIdx.x * 128 + threadIdx.x;            // 65536 rows
    const float4* p = (const float4*)(g_partial + (size_t)row * 32);
    float s = 0.f;
#pragma unroll
    for (int i = 0; i < 8; i++) {
        float4 v = p[i];
        s += (v.x + v.y) + (v.z + v.w);
    }
    g_rowsum[row] = 1.0f / s;
}

// ---------------- fp16 mma.sync GEMM ------------------------------------------
// 128x128 CTA tile, 128 threads = 4 warps (2x2), warp tile 64x64.
// 4-stage cp.async pipeline. Both operands K-major fp16; fp32 accumulate.
// MODE 0: g_xn @ Wt(which)^T -> q(/scale)/k/v half (+bias)
// MODE 1: Qs @ K^T -> exp -> g_p fp16 + row partial sums (per z)
// MODE 2: E @ Vt^T * (1/rowsum) -> g_attn half (per z)
// MODE 3: g_attn @ Wto^T     -> out fp32 (+bias)
constexpr int STG = 4;
constexpr int OPBYTES = 128 * 40 * 2;            // one operand tile: 10240 B
constexpr int STGBYTES = 2 * OPBYTES;            // A+B per stage: 20480 B
constexpr int GEMM_SMEM = STG * STGBYTES;        // 81920 B

template <int MODE>
__global__ __launch_bounds__(128, 2)
void gemm_tc(const float* __restrict__ bias, float* __restrict__ Cout, int which) {
    constexpr int K   = (MODE == 0) ? 512 : (MODE == 1) ? 512 : (MODE == 2) ? 2048 : 4096;
    constexpr int lda = (MODE == 2) ? 2048 : (MODE == 3) ? 4096 : 512;
    constexpr int ldb = (MODE == 2) ? 2048 : (MODE == 3) ? 4096 : 512;
    constexpr int T   = K / 32;

    extern __shared__ __half sh[];
    uint32_t sbase = smem_u32(sh);

    int tid = threadIdx.x;
    int lane = tid & 31, wid = tid >> 5;       // 4 warps
    int warp_m = wid & 1, warp_n = wid >> 1;   // 2 x 2 -> 64 x 64 per warp
    int z = blockIdx.z;
    int m0 = blockIdx.y * 128, n0 = blockIdx.x * 128;

    const __half* A;
    const __half* Bm;
    if (MODE == 0)      { A = g_xn;
                          Bm = (which == 0) ? g_wtq : (which == 1) ? g_wtk : g_wtv; }
    else if (MODE == 1) { A = g_q + (size_t)z * S_ * D_; Bm = g_k + (size_t)z * S_ * D_; }
    else if (MODE == 2) { A = g_p + ((size_t)z << 22);   Bm = g_vt + (size_t)z * S_ * D_; }
    else                { A = g_attn; Bm = g_wto; }
    A  += (size_t)m0 * lda;
    Bm += (size_t)n0 * ldb;

    float c[4][8][4];
#pragma unroll
    for (int i = 0; i < 4; i++)
#pragma unroll
        for (int j = 0; j < 8; j++)
#pragma unroll
            for (int e = 0; e < 4; e++) c[i][j][e] = 0.0f;

    // tile fill: 128 rows x 32 halves per operand = 512 x 16B each; 4+4 per thread
    int lrow = tid >> 2, lseg = tid & 3;       // lrow 0..31
    auto tile_load = [&](int stg, int k0) {
        uint32_t abase = sbase + (uint32_t)stg * STGBYTES;
        uint32_t bbase = abase + OPBYTES;
        uint32_t off = (uint32_t)lrow * 80 + (uint32_t)lseg * 16;
#pragma unroll
        for (int i = 0; i < 4; i++) {
            cp16(abase + off + (uint32_t)i * 32 * 80,
                 A + (size_t)(lrow + i * 32) * lda + k0 + lseg * 8);
            cp16(bbase + off + (uint32_t)i * 32 * 80,
                 Bm + (size_t)(lrow + i * 32) * ldb + k0 + lseg * 8);
        }
        CP_COMMIT();
    };

    // ldmatrix lane geometry (byte offsets within one operand tile)
    int rowA = warp_m * 64 + (lane & 7) + ((lane & 8) ? 8 : 0);
    int kA   = (lane & 16) ? 8 : 0;
    int rowB = warp_n * 64 + (lane & 7) + ((lane & 16) ? 8 : 0);
    int kB   = (lane & 8) ? 8 : 0;

    // prologue: prefetch STG-1 tiles
    tile_load(0, 0);
    tile_load(1, 32);
    tile_load(2, 64);

    for (int t = 0; t < T; t++) {
        int buf = t % STG;
        CP_WAIT2();                 // stage t landed (2 younger groups in flight)
        __syncthreads();            // all warps done with the buffer being refilled
        {
            int tn = t + STG - 1;
            if (tn < T) tile_load(tn % STG, tn * 32);
            else        CP_COMMIT();      // empty group keeps the wait count aligned
        }

        uint32_t abase = sbase + (uint32_t)buf * STGBYTES;
        uint32_t bbase = abase + OPBYTES;
#pragma unroll
        for (int kf = 0; kf < 2; kf++) {
            uint32_t a[4][4], b[4][4];
#pragma unroll
            for (int im = 0; im < 4; im++)
                ldsm_x4(a[im], abase + (uint32_t)(rowA + im * 16) * 80
                                     + (uint32_t)(kA + kf * 16) * 2);
#pragma unroll
            for (int jp = 0; jp < 4; jp++)
                ldsm_x4(b[jp], bbase + (uint32_t)(rowB + jp * 16) * 80
                                     + (uint32_t)(kB + kf * 16) * 2);
#pragma unroll
            for (int im = 0; im < 4; im++)
#pragma unroll
                for (int jn = 0; jn < 8; jn++)
                    mma_f16(c[im][jn], a[im], &b[jn >> 1][(jn & 1) * 2]);
        }
    }
    __syncthreads();

    // ---- epilogue: thread owns cols (cc, cc+1) at rows r0 and r0+8 ----
    float rs[4][2];
    if (MODE == 1) {
#pragma unroll
        for (int i = 0; i < 4; i++) { rs[i][0] = 0.f; rs[i][1] = 0.f; }
    }
#pragma unroll
    for (int im = 0; im < 4; im++) {
#pragma unroll
        for (int jn = 0; jn < 8; jn++) {
            int r0 = m0 + warp_m * 64 + im * 16 + (lane >> 2);
            int cc = n0 + warp_n * 64 + jn * 8 + (lane & 3) * 2;
            float2 lo = make_float2(c[im][jn][0], c[im][jn][1]);
            float2 hi = make_float2(c[im][jn][2], c[im][jn][3]);

            if (MODE == 0) {
                float2 bv = *(const float2*)&bias[cc];
                lo.x += bv.x; lo.y += bv.y;
                hi.x += bv.x; hi.y += bv.y;
                if (which == 0) {   // pre-scale Q
                    lo.x *= ATT_SCALE; lo.y *= ATT_SCALE;
                    hi.x *= ATT_SCALE; hi.y *= ATT_SCALE;
                }
                __half* C = (which == 0) ? g_q : (which == 1) ? g_k : g_v;
                int h = cc >> 9, d = cc & 511;
                int b0 = r0 >> 11, s0 = r0 & 2047;
                *(__half2*)(C + ((size_t)(b0 * 8 + h) * S_ + s0) * D_ + d) =
                    __floats2half2_rn(lo.x, lo.y);
                int b1 = (r0 + 8) >> 11, s1 = (r0 + 8) & 2047;
                *(__half2*)(C + ((size_t)(b1 * 8 + h) * S_ + s1) * D_ + d) =
                    __floats2half2_rn(hi.x, hi.y);
            } else if (MODE == 1) {
                // unnormalized softmax numerator: exp(logit), fp16 store
                float e0 = __expf(lo.x), e1 = __expf(lo.y);
                float e2 = __expf(hi.x), e3 = __expf(hi.y);
                rs[im][0] += e0 + e1;
                rs[im][1] += e2 + e3;
                __half* base = g_p + ((size_t)z << 22) + cc;
                *(__half2*)(base + (size_t)r0 * S_) = __floats2half2_rn(e0, e1);
                *(__half2*)(base + (size_t)(r0 + 8) * S_) = __floats2half2_rn(e2, e3);
            } else if (MODE == 2) {
                float inv0 = g_rowsum[(size_t)z * S_ + r0];
                float inv1 = g_rowsum[(size_t)z * S_ + r0 + 8];
                lo.x *= inv0; lo.y *= inv0;
                hi.x *= inv1; hi.y *= inv1;
                int b = z >> 3, h = z & 7;
                __half* base = g_attn + (size_t)(b * S_) * DH + h * 512 + cc;
                *(__half2*)(base + (size_t)r0 * DH) = __floats2half2_rn(lo.x, lo.y);
                *(__half2*)(base + (size_t)(r0 + 8) * DH) = __floats2half2_rn(hi.x, hi.y);
            } else {
                float2 bv = *(const float2*)&bias[cc];
                lo.x += bv.x; lo.y += bv.y;
                hi.x += bv.x; hi.y += bv.y;
                *(float2*)(Cout + (size_t)r0 * D_ + cc) = lo;
                *(float2*)(Cout + (size_t)(r0 + 8) * D_ + cc) = hi;
            }
        }
    }

    if (MODE == 1) {
        // quad-reduce: lanes sharing a row differ only in (lane & 3)
#pragma unroll
        for (int im = 0; im < 4; im++) {
#pragma unroll
            for (int h2 = 0; h2 < 2; h2++) {
                float v = rs[im][h2];
                v += __shfl_xor_sync(0xffffffffu, v, 1);
                v += __shfl_xor_sync(0xffffffffu, v, 2);
                if ((lane & 3) == 0) {
                    int grow = m0 + warp_m * 64 + im * 16 + (lane >> 2) + h2 * 8;
                    g_partial[((size_t)z * S_ + grow) * 32 + blockIdx.x * 2 + warp_n] = v;
                }
            }
        }
    }
}

// ---------------- launch ------------------------------------------------------
extern "C" void kernel_launch(void* const* d_in, const int* in_sizes, int n_in,
                              void* d_out, int out_size) {
    const float* x    = (const float*)d_in[0];
    const float* ln_w = (const float*)d_in[1];
    const float* ln_b = (const float*)d_in[2];
    const float* q_w  = (const float*)d_in[3];
    const float* q_b  = (const float*)d_in[4];
    const float* k_w  = (const float*)d_in[5];
    const float* k_b  = (const float*)d_in[6];
    const float* v_w  = (const float*)d_in[7];
    const float* v_b  = (const float*)d_in[8];
    const float* o_w  = (const float*)d_in[9];
    const float* o_b  = (const float*)d_in[10];
    float* out = (float*)d_out;

    static bool attr_done = false;
    if (!attr_done) {
        cudaFuncSetAttribute(gemm_tc<0>, cudaFuncAttributeMaxDynamicSharedMemorySize, GEMM_SMEM);
        cudaFuncSetAttribute(gemm_tc<1>, cudaFuncAttributeMaxDynamicSharedMemorySize, GEMM_SMEM);
        cudaFuncSetAttribute(gemm_tc<2>, cudaFuncAttributeMaxDynamicSharedMemorySize, GEMM_SMEM);
        cudaFuncSetAttribute(gemm_tc<3>, cudaFuncAttributeMaxDynamicSharedMemorySize, GEMM_SMEM);
        attr_done = true;
    }

    dim3 tb(32, 8);
    ln_kernel<<<NT, 128>>>(x, ln_w, ln_b);
    transpose_kernel<<<dim3(128, 16, 1), tb>>>(q_w, 0, 512, 4096);
    transpose_kernel<<<dim3(128, 16, 1), tb>>>(k_w, 1, 512, 4096);
    transpose_kernel<<<dim3(128, 16, 1), tb>>>(v_w, 2, 512, 4096);
    transpose_kernel<<<dim3(16, 128, 1), tb>>>(o_w, 3, 4096, 512);

    dim3 gQKV(DH / 128, NT / 128, 1);                      // (32, 64)
    gemm_tc<0><<<gQKV, 128, GEMM_SMEM>>>(q_b, nullptr, 0);
    gemm_tc<0><<<gQKV, 128, GEMM_SMEM>>>(k_b, nullptr, 1);
    gemm_tc<0><<<gQKV, 128, GEMM_SMEM>>>(v_b, nullptr, 2);

    // V transpose per z: [2048,512] -> [512,2048]
    transpose_kernel<<<dim3(16, 64, ZN), tb>>>(nullptr, 4, 2048, 512);

    dim3 gS(S_ / 128, S_ / 128, ZN);                       // (16, 16, 32)
    gemm_tc<1><<<gS, 128, GEMM_SMEM>>>(nullptr, nullptr, 0);

    rowsum_kernel<<<ZN * S_ / 128, 128>>>();

    dim3 gPV(D_ / 128, S_ / 128, ZN);                      // (4, 16, 32)
    gemm_tc<2><<<gPV, 128, GEMM_SMEM>>>(nullptr, nullptr, 0);

    dim3 gO(D_ / 128, NT / 128, 1);                        // (4, 64)
    gemm_tc<3><<<gO, 128, GEMM_SMEM>>>(o_b, out, 0);
}